// round 16
// baseline (speedup 1.0000x reference)
#include <cuda_runtime.h>

// Problem constants
#define B_SZ    4096
#define NBRANCH 64
#define DIM     512
#define INTER   128
#define EPSI    1e-5f

// Tiling
#define BM      32          // batch rows per CTA
#define NSPLIT  4           // branch groups (CTAs per batch tile)
#define NPER    (NBRANCH / NSPLIT)
#define KT1     32          // K-tile for GEMM1 (K=512)
#define KT2     16          // K-tile for GEMM2 (K=128)
#define W1S     36          // SMEM row stride (floats) for W1 tile (16B-aligned, conflict-free)
#define W2S     20          // SMEM row stride for W2 tile
#define HS      132         // SMEM row stride for h tile

#define SMEM_FLOATS (BM*DIM + BM*HS + INTER*W1S + DIM*W2S)
#define SMEM_BYTES  (SMEM_FLOATS * 4)

// Scratch (device globals: allocation-free per harness rules)
__device__ float g_s[B_SZ * DIM];            // 8 MB: s = sum_n t
__device__ float g_sc1[NBRANCH * INTER];
__device__ float g_sh1[NBRANCH * INTER];
__device__ float g_sc2[NBRANCH * DIM];
__device__ float g_sh2[NBRANCH * DIM];

// ---------------------------------------------------------------------------
// K0: fold BN params into affine scale/shift.
//   h = (Wx + b - m)*rs*g + beta  =  (Wx)*sc + sh,  sc = g*rs, sh = beta + (b-m)*sc
// ---------------------------------------------------------------------------
__global__ void affine_kernel(const float* __restrict__ b1, const float* __restrict__ g1,
                              const float* __restrict__ be1, const float* __restrict__ m1,
                              const float* __restrict__ v1,
                              const float* __restrict__ b2, const float* __restrict__ g2,
                              const float* __restrict__ be2, const float* __restrict__ m2,
                              const float* __restrict__ v2) {
    int i = blockIdx.x * blockDim.x + threadIdx.x;
    if (i < NBRANCH * INTER) {
        float sc = g1[i] * rsqrtf(v1[i] + EPSI);
        g_sc1[i] = sc;
        g_sh1[i] = be1[i] + (b1[i] - m1[i]) * sc;
    }
    if (i < NBRANCH * DIM) {
        float sc = g2[i] * rsqrtf(v2[i] + EPSI);
        g_sc2[i] = sc;
        g_sh2[i] = be2[i] + (b2[i] - m2[i]) * sc;
    }
}

// ---------------------------------------------------------------------------
// K1: s[b,d] = sum_n t[b,n,d]   (HBM-bound, 536 MB read)
// ---------------------------------------------------------------------------
__global__ void sum_kernel(const float* __restrict__ t) {
    int idx = blockIdx.x * 256 + threadIdx.x;   // over B*DIM
    int b = idx >> 9;
    int d = idx & (DIM - 1);
    const float* p = t + (size_t)b * NBRANCH * DIM + d;
    float acc = 0.f;
#pragma unroll
    for (int n = 0; n < NBRANCH; n++) acc += p[n * DIM];
    g_s[idx] = acc;
}

// ---------------------------------------------------------------------------
// K2: fused grouped GEMM1 -> BN1/relu -> GEMM2 -> BN2/sigmoid -> *t -> sum_n
// CTA = (32 batch rows) x (16 branches). out accumulated in registers,
// flushed once via atomicAdd (NSPLIT=4 partials per output element).
// ---------------------------------------------------------------------------
__global__ __launch_bounds__(256, 1)
void fused_kernel(const float* __restrict__ t,
                  const float* __restrict__ W1,
                  const float* __restrict__ W2,
                  float* __restrict__ out) {
    extern __shared__ float smem[];
    float* s_s  = smem;                       // [BM][DIM]
    float* h_s  = s_s  + BM * DIM;            // [BM][HS]
    float* w1_s = h_s  + BM * HS;             // [INTER][W1S]
    float* w2_s = w1_s + INTER * W1S;         // [DIM][W2S]

    const int tid  = threadIdx.x;
    const int b0   = blockIdx.x * BM;
    const int n0   = blockIdx.y * NPER;
    const int rowg = tid >> 5;                // 0..7  (4 rows each)
    const int colg = tid & 31;                // 0..31

    // Load s tile: 32x512 floats (64 KB), coalesced float4
#pragma unroll
    for (int q = 0; q < 16; q++) {
        int idx = tid + 256 * q;
        int row = idx >> 7;
        int d4  = (idx & 127) << 2;
        *(float4*)&s_s[row * DIM + d4] =
            *(const float4*)&g_s[(size_t)(b0 + row) * DIM + d4];
    }

    float out_acc[4][16];
#pragma unroll
    for (int rr = 0; rr < 4; rr++)
#pragma unroll
        for (int j = 0; j < 16; j++) out_acc[rr][j] = 0.f;

    for (int nn = 0; nn < NPER; ++nn) {
        const int n = n0 + nn;
        const float* W1n = W1 + (size_t)n * INTER * DIM;
        const float* W2n = W2 + (size_t)n * DIM * INTER;

        // ---------------- GEMM1: h(32x128) = s(32x512) @ W1[n]^T -----------
        float acc1[4][4];
#pragma unroll
        for (int rr = 0; rr < 4; rr++)
#pragma unroll
            for (int j = 0; j < 4; j++) acc1[rr][j] = 0.f;

        for (int kt = 0; kt < DIM; kt += KT1) {
            __syncthreads();
#pragma unroll
            for (int q = 0; q < 4; q++) {
                int idx = tid + 256 * q;          // 1024 float4 = 128x32 floats
                int ir  = idx >> 3;               // 0..127  (inter row)
                int kk4 = (idx & 7) << 2;         // 0..28
                *(float4*)&w1_s[ir * W1S + kk4] =
                    *(const float4*)&W1n[(size_t)ir * DIM + kt + kk4];
            }
            __syncthreads();
#pragma unroll
            for (int kk = 0; kk < KT1; kk += 4) {
                float4 sv[4];
#pragma unroll
                for (int rr = 0; rr < 4; rr++)
                    sv[rr] = *(float4*)&s_s[(rowg * 4 + rr) * DIM + kt + kk];
#pragma unroll
                for (int j = 0; j < 4; j++) {
                    float4 wv = *(float4*)&w1_s[(colg + 32 * j) * W1S + kk];
#pragma unroll
                    for (int rr = 0; rr < 4; rr++) {
                        acc1[rr][j] += sv[rr].x * wv.x + sv[rr].y * wv.y +
                                       sv[rr].z * wv.z + sv[rr].w * wv.w;
                    }
                }
            }
        }

        // affine + relu -> h_s  (prior GEMM2 readers are past the k-tile
        // barriers above, so this write is race-free; GEMM2's first barrier
        // below publishes it)
#pragma unroll
        for (int j = 0; j < 4; j++) {
            int col = colg + 32 * j;
            float sc = g_sc1[n * INTER + col];
            float sh = g_sh1[n * INTER + col];
#pragma unroll
            for (int rr = 0; rr < 4; rr++) {
                float hv = fmaxf(acc1[rr][j] * sc + sh, 0.f);
                h_s[(rowg * 4 + rr) * HS + col] = hv;
            }
        }

        // ---------------- GEMM2: y(32x512) = h(32x128) @ W2[n]^T -----------
        float acc2[4][16];
#pragma unroll
        for (int rr = 0; rr < 4; rr++)
#pragma unroll
            for (int j = 0; j < 16; j++) acc2[rr][j] = 0.f;

        for (int kt = 0; kt < INTER; kt += KT2) {
            __syncthreads();
#pragma unroll
            for (int q = 0; q < 8; q++) {
                int idx = tid + 256 * q;          // 2048 float4 = 512x16 floats
                int dr  = idx >> 2;               // 0..511 (dim row)
                int ii4 = (idx & 3) << 2;         // 0..12
                *(float4*)&w2_s[dr * W2S + ii4] =
                    *(const float4*)&W2n[(size_t)dr * INTER + kt + ii4];
            }
            __syncthreads();
#pragma unroll
            for (int kk = 0; kk < KT2; kk += 4) {
                float4 hv[4];
#pragma unroll
                for (int rr = 0; rr < 4; rr++)
                    hv[rr] = *(float4*)&h_s[(rowg * 4 + rr) * HS + kt + kk];
#pragma unroll
                for (int j = 0; j < 16; j++) {
                    float4 wv = *(float4*)&w2_s[(colg + 32 * j) * W2S + kk];
#pragma unroll
                    for (int rr = 0; rr < 4; rr++) {
                        acc2[rr][j] += hv[rr].x * wv.x + hv[rr].y * wv.y +
                                       hv[rr].z * wv.z + hv[rr].w * wv.w;
                    }
                }
            }
        }

        // ---------------- epilogue: BN2 -> sigmoid -> * t -> accumulate ----
#pragma unroll
        for (int j = 0; j < 16; j++) {
            int col = colg + 32 * j;
            float sc = g_sc2[n * DIM + col];
            float sh = g_sh2[n * DIM + col];
#pragma unroll
            for (int rr = 0; rr < 4; rr++) {
                int row = b0 + rowg * 4 + rr;
                float y = acc2[rr][j] * sc + sh;
                float w = 1.f / (1.f + __expf(-y));
                float tv = t[((size_t)row * NBRANCH + n) * DIM + col];
                out_acc[rr][j] += w * tv;
            }
        }
    }

    // Flush: 4 partial CTAs per (b,d) -> atomicAdd (out pre-zeroed)
#pragma unroll
    for (int j = 0; j < 16; j++) {
        int col = colg + 32 * j;
#pragma unroll
        for (int rr = 0; rr < 4; rr++) {
            int row = b0 + rowg * 4 + rr;
            atomicAdd(&out[(size_t)row * DIM + col], out_acc[rr][j] * 3.f);
        }
    }
}

// ---------------------------------------------------------------------------
// Inputs (metadata order): t, W1, b1, g1, beta1, m1, v1, W2, b2, g2, beta2, m2, v2
// ---------------------------------------------------------------------------
extern "C" void kernel_launch(void* const* d_in, const int* in_sizes, int n_in,
                              void* d_out, int out_size) {
    const float* t    = (const float*)d_in[0];
    const float* W1   = (const float*)d_in[1];
    const float* b1   = (const float*)d_in[2];
    const float* g1   = (const float*)d_in[3];
    const float* be1  = (const float*)d_in[4];
    const float* m1   = (const float*)d_in[5];
    const float* v1   = (const float*)d_in[6];
    const float* W2   = (const float*)d_in[7];
    const float* b2   = (const float*)d_in[8];
    const float* g2   = (const float*)d_in[9];
    const float* be2  = (const float*)d_in[10];
    const float* m2   = (const float*)d_in[11];
    const float* v2   = (const float*)d_in[12];
    float* out = (float*)d_out;

    cudaFuncSetAttribute(fused_kernel, cudaFuncAttributeMaxDynamicSharedMemorySize,
                         SMEM_BYTES);

    cudaMemsetAsync(d_out, 0, (size_t)out_size * sizeof(float), 0);

    affine_kernel<<<(NBRANCH * DIM + 255) / 256, 256>>>(b1, g1, be1, m1, v1,
                                                        b2, g2, be2, m2, v2);

    sum_kernel<<<(B_SZ * DIM) / 256, 256>>>(t);

    dim3 grid(B_SZ / BM, NSPLIT);
    fused_kernel<<<grid, 256, SMEM_BYTES>>>(t, W1, W2, out);
}